// round 12
// baseline (speedup 1.0000x reference)
#include <cuda_runtime.h>
#include <math.h>
#include <stdint.h>

#define NB   32      // batch
#define NT   4096    // sequence
#define NCAT 128
#define NNE  512
#define NHS  64

#define CHR  8                        // rows per chunk
#define CPB  8                        // chunks per block
#define NBPB 64                       // blocks per batch = NT/(CHR*CPB)
#define CHUNK_BYTES (CHR * NNE * 4)   // 16384
#define ROWS_PB (CHR * CPB)           // 64 output rows per block

// ---- scratch (device globals; no allocations allowed) ----
__device__ float g_qk[NB * NNE];
__device__ float g_pm[NB * NBPB];
__device__ float g_ps[NB * NBPB];
__device__ float g_pacc[(size_t)NB * NBPB * NNE];  // 4 MB
__device__ float g_y[NB * NNE];
__device__ int   g_cnt[NB];
__device__ int   g_flag[NB];

// ============================================================
// Kernel A: q = cat_emb@Wq ; qk[n] = 0.125 * Wk[n,:]·q
// also resets per-batch counter/flag for the mega kernel.
// ============================================================
__global__ void kA(const float* __restrict__ cat_emb,
                   const float* __restrict__ Wq,
                   const float* __restrict__ Wk) {
    const int b = blockIdx.x;
    const int tid = threadIdx.x;
    const int h = tid & 63;
    const int part = tid >> 6;

    if (tid == 0) { g_cnt[b] = 0; g_flag[b] = 0; }

    __shared__ float qpart[8][NHS];
    __shared__ float qs[NHS];

    float a = 0.f;
    const float* ce = cat_emb + b * NCAT;
    #pragma unroll
    for (int c = part * 16; c < part * 16 + 16; ++c)
        a += ce[c] * Wq[c * NHS + h];
    qpart[part][h] = a;
    __syncthreads();

    if (tid < NHS) {
        float q = 0.f;
        #pragma unroll
        for (int p = 0; p < 8; ++p) q += qpart[p][tid];
        qs[tid] = q * 0.125f;
    }
    __syncthreads();

    const float4* wk4 = reinterpret_cast<const float4*>(Wk + tid * NHS);
    const float4* q4  = reinterpret_cast<const float4*>(qs);
    float acc = 0.f;
    #pragma unroll
    for (int i = 0; i < 16; ++i) {
        const float4 w = wk4[i];
        const float4 qq = q4[i];
        acc += w.x * qq.x + w.y * qq.y + w.z * qq.z + w.w * qq.w;
    }
    g_qk[b * NNE + tid] = acc;
}

// ============================================================
// TMA helpers
// ============================================================
__device__ __forceinline__ void bulk_copy(uint32_t dst_smem, const float* src,
                                          uint32_t mbar) {
    asm volatile("mbarrier.arrive.expect_tx.shared.b64 _, [%0], %1;"
                 :: "r"(mbar), "r"((uint32_t)CHUNK_BYTES) : "memory");
    asm volatile(
        "cp.async.bulk.shared::cluster.global.mbarrier::complete_tx::bytes "
        "[%0], [%1], %2, [%3];"
        :: "r"(dst_smem), "l"(src), "r"((uint32_t)CHUNK_BYTES), "r"(mbar)
        : "memory");
}

__device__ __forceinline__ void mbar_wait(uint32_t mbar, uint32_t parity) {
    uint32_t done;
    asm volatile(
        "{\n\t.reg .pred p;\n\t"
        "mbarrier.try_wait.parity.acquire.cta.shared::cta.b64 p, [%1], %2;\n\t"
        "selp.b32 %0, 1, 0, p;\n\t}"
        : "=r"(done) : "r"(mbar), "r"(parity) : "memory");
    while (!done) {
        asm volatile(
            "{\n\t.reg .pred p;\n\t"
            "mbarrier.try_wait.parity.acquire.cta.shared::cta.b64 p, [%1], %2, 0x989680;\n\t"
            "selp.b32 %0, 1, 0, p;\n\t}"
            : "=r"(done) : "r"(mbar), "r"(parity) : "memory");
    }
}

// ============================================================
// Mega kernel: R10 fuse (TMA double-buffer, online softmax) +
// per-batch last-block epilogue (kE) + per-block broadcast write (kF).
// grid: (NBPB, NB) = 2048 blocks, 256 threads, 32 KB ring (reused by epilogue).
// ============================================================
__global__ void __launch_bounds__(256) kMega(
    const float* __restrict__ x,
    const float* __restrict__ Wv,
    const float* __restrict__ Wp,
    const float* __restrict__ gamma,
    const float* __restrict__ beta,
    float* __restrict__ out)
{
    const int b = blockIdx.y;
    const int blk = blockIdx.x;
    const int tid = threadIdx.x;
    const int warp = tid >> 5, lane = tid & 31;

    __shared__ __align__(128) float sx[2][CHR * NNE];   // 32 KB (reused later)
    __shared__ float sscore[CHR];
    __shared__ __align__(8) unsigned long long mbar[2];
    __shared__ int s_last;

    const uint32_t sx_a0 = (uint32_t)__cvta_generic_to_shared(sx[0]);
    const uint32_t sx_a1 = (uint32_t)__cvta_generic_to_shared(sx[1]);
    const uint32_t mb_a0 = (uint32_t)__cvta_generic_to_shared(&mbar[0]);
    const uint32_t mb_a1 = (uint32_t)__cvta_generic_to_shared(&mbar[1]);

    const float* xbase = x + ((size_t)b * NT + (size_t)blk * ROWS_PB) * NNE;

    if (tid == 0) {
        asm volatile("mbarrier.init.shared.b64 [%0], 1;" :: "r"(mb_a0) : "memory");
        asm volatile("mbarrier.init.shared.b64 [%0], 1;" :: "r"(mb_a1) : "memory");
        asm volatile("fence.proxy.async.shared::cta;" ::: "memory");
    }
    __syncthreads();

    if (tid == 0) {
        bulk_copy(sx_a0, xbase,                     mb_a0);
        bulk_copy(sx_a1, xbase + (size_t)CHR * NNE, mb_a1);
    }

    const float4* qkp = reinterpret_cast<const float4*>(g_qk + b * NNE);
    float4 qv[4];
    #pragma unroll
    for (int i = 0; i < 4; ++i) qv[i] = qkp[lane + 32 * i];

    float M = -INFINITY, S = 0.f, a0 = 0.f, a1 = 0.f;

    #pragma unroll
    for (int c = 0; c < CPB; ++c) {
        const int buf = c & 1;
        mbar_wait(buf ? mb_a1 : mb_a0, (c >> 1) & 1);

        const float* sb = sx[buf];
        const float4* sb4 = reinterpret_cast<const float4*>(sb);

        // score for row t = warp
        float d = 0.f;
        #pragma unroll
        for (int i = 0; i < 4; ++i) {
            const float4 xv = sb4[warp * (NNE / 4) + lane + 32 * i];
            d += xv.x * qv[i].x + xv.y * qv[i].y +
                 xv.z * qv[i].z + xv.w * qv[i].w;
        }
        #pragma unroll
        for (int o = 16; o > 0; o >>= 1)
            d += __shfl_xor_sync(0xffffffffu, d, o);
        if (lane == 0) sscore[warp] = d;
        __syncthreads();

        // chunk softmax + running rescale (redundant per warp)
        const float s = sscore[lane & 7];
        float mc = s;
        #pragma unroll
        for (int o = 4; o > 0; o >>= 1)
            mc = fmaxf(mc, __shfl_xor_sync(0xffffffffu, mc, o));
        const float newM = fmaxf(M, mc);
        const float f = __expf(M - newM);
        const float e = __expf(s - newM);
        float Ssum = e;
        #pragma unroll
        for (int o = 4; o > 0; o >>= 1)
            Ssum += __shfl_xor_sync(0xffffffffu, Ssum, o);
        S = S * f + Ssum;
        a0 *= f;
        a1 *= f;
        M = newM;

        #pragma unroll
        for (int t = 0; t < CHR; ++t) {
            const float wt = __shfl_sync(0xffffffffu, e, t);
            a0 = fmaf(wt, sb[t * NNE + tid],       a0);
            a1 = fmaf(wt, sb[t * NNE + tid + 256], a1);
        }
        __syncthreads();

        if (c + 2 < CPB && tid == 0) {
            bulk_copy(buf ? sx_a1 : sx_a0,
                      xbase + (size_t)(c + 2) * CHR * NNE,
                      buf ? mb_a1 : mb_a0);
        }
    }

    // ---- publish partial ----
    {
        float* p = g_pacc + (size_t)(b * NBPB + blk) * NNE;
        p[tid]       = a0;
        p[tid + 256] = a1;
        if (tid == 0) {
            g_pm[b * NBPB + blk] = M;
            g_ps[b * NBPB + blk] = S;
        }
    }
    __threadfence();
    __syncthreads();   // partials stored; sx ring dead -> reusable

    if (tid == 0)
        s_last = (atomicAdd(&g_cnt[b], 1) == NBPB - 1) ? 1 : 0;
    __syncthreads();

    if (s_last) {
        // ========== epilogue (kE) by the last block of batch b ==========
        __threadfence();  // acquire side of the counter protocol
        float* ep = sx[0];                 // reuse ring smem
        float* spm   = ep;                 // 64
        float* sps   = ep + 64;            // 64
        float* sf    = ep + 128;           // 64
        float* xa    = ep + 192;           // 512
        float* outh  = ep + 704;           // 64
        float* red   = ep + 768;           // 32
        float* bcast = ep + 800;           // 1
        float* wpart = ep + 832;           // 4*64
        float4* xpart = reinterpret_cast<float4*>(ep + 1088);  // 2*128 float4

        if (tid < NBPB) {
            spm[tid] = g_pm[b * NBPB + tid];
            sps[tid] = g_ps[b * NBPB + tid];
        }
        __syncthreads();

        float mb2 = -INFINITY;
        #pragma unroll 8
        for (int c = 0; c < NBPB; ++c) mb2 = fmaxf(mb2, spm[c]);
        if (tid < NBPB) sf[tid] = __expf(spm[tid] - mb2);
        __syncthreads();

        float Sb = 0.f;
        #pragma unroll 8
        for (int c = 0; c < NBPB; ++c) Sb += sps[c] * sf[c];

        {
            const int col4 = tid & 127;
            const int part = tid >> 7;      // 2 parts x 32 partials
            const float4* pp = reinterpret_cast<const float4*>(
                g_pacc + (size_t)(b * NBPB + part * 32) * NNE);
            const float* f = sf + part * 32;
            float4 acc4 = make_float4(0.f, 0.f, 0.f, 0.f);
            #pragma unroll 8
            for (int c = 0; c < 32; ++c) {
                const float4 v = pp[(size_t)c * 128 + col4];
                const float fc = f[c];
                acc4.x = fmaf(v.x, fc, acc4.x);
                acc4.y = fmaf(v.y, fc, acc4.y);
                acc4.z = fmaf(v.z, fc, acc4.z);
                acc4.w = fmaf(v.w, fc, acc4.w);
            }
            xpart[part * 128 + col4] = acc4;
        }
        __syncthreads();
        if (tid < 128) {
            float4 v0 = xpart[tid], v1 = xpart[128 + tid];
            const float inv = 1.f / Sb;
            reinterpret_cast<float4*>(xa)[tid] = make_float4(
                (v0.x + v1.x) * inv, (v0.y + v1.y) * inv,
                (v0.z + v1.z) * inv, (v0.w + v1.w) * inv);
        }
        __syncthreads();

        {
            const int h = tid & 63;
            const int part = tid >> 6;      // 4 parts x 128 n
            float po = 0.f;
            #pragma unroll 8
            for (int n = part * 128; n < part * 128 + 128; ++n)
                po = fmaf(xa[n], Wv[n * NHS + h], po);
            wpart[part * NHS + h] = po;
        }
        __syncthreads();
        if (tid < NHS) {
            float o = 0.f;
            #pragma unroll
            for (int p = 0; p < 4; ++p) o += wpart[p * NHS + tid];
            outh[tid] = o;
        }
        __syncthreads();

        float y0 = 0.f, y1 = 0.f;
        #pragma unroll
        for (int h2 = 0; h2 < NHS; ++h2) {
            const float oh = outh[h2];
            y0 = fmaf(oh, Wp[h2 * NNE + tid],       y0);
            y1 = fmaf(oh, Wp[h2 * NNE + tid + 256], y1);
        }

        // LayerNorm over 512 values (2 per thread)
        float s = y0 + y1;
        #pragma unroll
        for (int o = 16; o > 0; o >>= 1)
            s += __shfl_xor_sync(0xffffffffu, s, o);
        if (lane == 0) red[warp] = s;
        __syncthreads();
        if (tid < 8) {
            float t2 = red[tid];
            #pragma unroll
            for (int o = 4; o > 0; o >>= 1)
                t2 += __shfl_xor_sync(0xffu, t2, o);
            if (tid == 0) *bcast = t2;
        }
        __syncthreads();
        const float mu = *bcast * (1.f / NNE);
        __syncthreads();

        const float d0 = y0 - mu, d1 = y1 - mu;
        float vs = d0 * d0 + d1 * d1;
        #pragma unroll
        for (int o = 16; o > 0; o >>= 1)
            vs += __shfl_xor_sync(0xffffffffu, vs, o);
        if (lane == 0) red[warp] = vs;
        __syncthreads();
        if (tid < 8) {
            float t2 = red[tid];
            #pragma unroll
            for (int o = 4; o > 0; o >>= 1)
                t2 += __shfl_xor_sync(0xffu, t2, o);
            if (tid == 0) *bcast = t2;
        }
        __syncthreads();
        const float rstd = rsqrtf(*bcast * (1.f / NNE) + 1e-5f);

        g_y[b * NNE + tid]       = d0 * rstd * gamma[tid]       + beta[tid];
        g_y[b * NNE + tid + 256] = d1 * rstd * gamma[tid + 256] + beta[tid + 256];
        __threadfence();
        __syncthreads();
        if (tid == 0) atomicExch(&g_flag[b], 1);
    } else {
        // wait for the epilogue of this batch
        if (tid == 0) {
            while (atomicAdd(&g_flag[b], 0) == 0) __nanosleep(128);
            __threadfence();
        }
        __syncthreads();
    }

    // ========== broadcast write (kF) for this block's 64-row slice ==========
    {
        const int col = tid & 127;
        const int half = tid >> 7;
        const float4 val = reinterpret_cast<const float4*>(g_y + b * NNE)[col];
        float4* o = reinterpret_cast<float4*>(
            out + ((size_t)b * NT + (size_t)blk * ROWS_PB) * NNE);
        #pragma unroll 8
        for (int r = 0; r < ROWS_PB / 2; ++r)
            __stcs(&o[(size_t)(r * 2 + half) * (NNE / 4) + col], val);
    }
}

// ============================================================
extern "C" void kernel_launch(void* const* d_in, const int* in_sizes, int n_in,
                              void* d_out, int out_size) {
    const float* x       = (const float*)d_in[0];
    const float* cat_emb = (const float*)d_in[1];
    const float* Wq      = (const float*)d_in[2];
    const float* Wk      = (const float*)d_in[3];
    const float* Wv      = (const float*)d_in[4];
    const float* Wp      = (const float*)d_in[5];
    const float* gamma   = (const float*)d_in[6];
    const float* beta    = (const float*)d_in[7];
    float* out = (float*)d_out;

    kA<<<NB, 512>>>(cat_emb, Wq, Wk);
    kMega<<<dim3(NBPB, NB), 256>>>(x, Wv, Wp, gamma, beta, out);
}

// round 13
// speedup vs baseline: 1.4092x; 1.4092x over previous
#include <cuda_runtime.h>
#include <math.h>
#include <stdint.h>

#define NB   32      // batch
#define NT   4096    // sequence
#define NCAT 128
#define NNE  512
#define NHS  64

#define CHR  8                        // rows per chunk
#define CPB  16                       // chunks per block (single-wave grid)
#define NBPB 32                       // blocks per batch = NT/(CHR*CPB)
#define CHUNK_BYTES (CHR * NNE * 4)   // 16384

// ---- scratch (device globals; no allocations allowed) ----
__device__ float g_qk[NB * NNE];
__device__ float g_pm[NB * NBPB];
__device__ float g_ps[NB * NBPB];
__device__ float g_pacc[(size_t)NB * NBPB * NNE];  // 2 MB
__device__ float g_y[NB * NNE];

// ============================================================
// Kernel A: q = cat_emb@Wq ; qk[n] = 0.125 * Wk[n,:]·q
// ============================================================
__global__ void kA(const float* __restrict__ cat_emb,
                   const float* __restrict__ Wq,
                   const float* __restrict__ Wk) {
    const int b = blockIdx.x;
    const int tid = threadIdx.x;
    const int h = tid & 63;
    const int part = tid >> 6;

    __shared__ float qpart[8][NHS];
    __shared__ float qs[NHS];

    float a = 0.f;
    const float* ce = cat_emb + b * NCAT;
    #pragma unroll
    for (int c = part * 16; c < part * 16 + 16; ++c)
        a += ce[c] * Wq[c * NHS + h];
    qpart[part][h] = a;
    __syncthreads();

    if (tid < NHS) {
        float q = 0.f;
        #pragma unroll
        for (int p = 0; p < 8; ++p) q += qpart[p][tid];
        qs[tid] = q * 0.125f;
    }
    __syncthreads();

    const float4* wk4 = reinterpret_cast<const float4*>(Wk + tid * NHS);
    const float4* q4  = reinterpret_cast<const float4*>(qs);
    float acc = 0.f;
    #pragma unroll
    for (int i = 0; i < 16; ++i) {
        const float4 w = wk4[i];
        const float4 qq = q4[i];
        acc += w.x * qq.x + w.y * qq.y + w.z * qq.z + w.w * qq.w;
    }
    g_qk[b * NNE + tid] = acc;
}

// ============================================================
// TMA helpers
// ============================================================
__device__ __forceinline__ void bulk_copy(uint32_t dst_smem, const float* src,
                                          uint32_t mbar) {
    asm volatile("mbarrier.arrive.expect_tx.shared.b64 _, [%0], %1;"
                 :: "r"(mbar), "r"((uint32_t)CHUNK_BYTES) : "memory");
    asm volatile(
        "cp.async.bulk.shared::cluster.global.mbarrier::complete_tx::bytes "
        "[%0], [%1], %2, [%3];"
        :: "r"(dst_smem), "l"(src), "r"((uint32_t)CHUNK_BYTES), "r"(mbar)
        : "memory");
}

__device__ __forceinline__ void mbar_wait(uint32_t mbar, uint32_t parity) {
    uint32_t done;
    asm volatile(
        "{\n\t.reg .pred p;\n\t"
        "mbarrier.try_wait.parity.acquire.cta.shared::cta.b64 p, [%1], %2;\n\t"
        "selp.b32 %0, 1, 0, p;\n\t}"
        : "=r"(done) : "r"(mbar), "r"(parity) : "memory");
    while (!done) {
        asm volatile(
            "{\n\t.reg .pred p;\n\t"
            "mbarrier.try_wait.parity.acquire.cta.shared::cta.b64 p, [%1], %2, 0x989680;\n\t"
            "selp.b32 %0, 1, 0, p;\n\t}"
            : "=r"(done) : "r"(mbar), "r"(parity) : "memory");
    }
}

// ============================================================
// Fused kernel v9: R10 structure, single-wave grid (1024 blocks).
// double-buffered TMA (2 x 16 KB), 8-row chunks, in-register
// cross-chunk online-softmax accumulation.
// grid: (NBPB, NB), 256 threads (8 warps), 32 KB smem.
// ============================================================
__global__ void kFuse9(const float* __restrict__ x) {
    const int b = blockIdx.y;
    const int blk = blockIdx.x;
    const int tid = threadIdx.x;
    const int warp = tid >> 5, lane = tid & 31;

    __shared__ __align__(128) float sx[2][CHR * NNE];   // 32 KB
    __shared__ float sscore[CHR];
    __shared__ __align__(8) unsigned long long mbar[2];

    const uint32_t sx_a0 = (uint32_t)__cvta_generic_to_shared(sx[0]);
    const uint32_t sx_a1 = (uint32_t)__cvta_generic_to_shared(sx[1]);
    const uint32_t mb_a0 = (uint32_t)__cvta_generic_to_shared(&mbar[0]);
    const uint32_t mb_a1 = (uint32_t)__cvta_generic_to_shared(&mbar[1]);

    const float* xbase = x + ((size_t)b * NT + (size_t)blk * CHR * CPB) * NNE;

    if (tid == 0) {
        asm volatile("mbarrier.init.shared.b64 [%0], 1;" :: "r"(mb_a0) : "memory");
        asm volatile("mbarrier.init.shared.b64 [%0], 1;" :: "r"(mb_a1) : "memory");
        asm volatile("fence.proxy.async.shared::cta;" ::: "memory");
    }
    __syncthreads();

    if (tid == 0) {
        bulk_copy(sx_a0, xbase,                     mb_a0);
        bulk_copy(sx_a1, xbase + (size_t)CHR * NNE, mb_a1);
    }

    // qk into registers while copies are in flight
    const float4* qkp = reinterpret_cast<const float4*>(g_qk + b * NNE);
    float4 qv[4];
    #pragma unroll
    for (int i = 0; i < 4; ++i) qv[i] = qkp[lane + 32 * i];

    float M = -INFINITY, S = 0.f, a0 = 0.f, a1 = 0.f;

    #pragma unroll
    for (int c = 0; c < CPB; ++c) {
        const int buf = c & 1;
        mbar_wait(buf ? mb_a1 : mb_a0, (c >> 1) & 1);

        const float* sb = sx[buf];
        const float4* sb4 = reinterpret_cast<const float4*>(sb);

        // ---- score for row t = warp ----
        float d = 0.f;
        #pragma unroll
        for (int i = 0; i < 4; ++i) {
            const float4 xv = sb4[warp * (NNE / 4) + lane + 32 * i];
            d += xv.x * qv[i].x + xv.y * qv[i].y +
                 xv.z * qv[i].z + xv.w * qv[i].w;
        }
        #pragma unroll
        for (int o = 16; o > 0; o >>= 1)
            d += __shfl_xor_sync(0xffffffffu, d, o);
        if (lane == 0) sscore[warp] = d;
        __syncthreads();

        // ---- chunk softmax + running rescale (redundant per warp) ----
        const float s = sscore[lane & 7];
        float mc = s;
        #pragma unroll
        for (int o = 4; o > 0; o >>= 1)
            mc = fmaxf(mc, __shfl_xor_sync(0xffffffffu, mc, o));
        const float newM = fmaxf(M, mc);
        const float f = __expf(M - newM);
        const float e = __expf(s - newM);
        float Ssum = e;
        #pragma unroll
        for (int o = 4; o > 0; o >>= 1)
            Ssum += __shfl_xor_sync(0xffffffffu, Ssum, o);
        S = S * f + Ssum;
        a0 *= f;
        a1 *= f;
        M = newM;

        // ---- weighted column sums ----
        #pragma unroll
        for (int t = 0; t < CHR; ++t) {
            const float wt = __shfl_sync(0xffffffffu, e, t);
            a0 = fmaf(wt, sb[t * NNE + tid],       a0);
            a1 = fmaf(wt, sb[t * NNE + tid + 256], a1);
        }
        __syncthreads();  // all reads of buf done before refill

        if (c + 2 < CPB && tid == 0) {
            bulk_copy(buf ? sx_a1 : sx_a0,
                      xbase + (size_t)(c + 2) * CHR * NNE,
                      buf ? mb_a1 : mb_a0);
        }
    }

    float* p = g_pacc + (size_t)(b * NBPB + blk) * NNE;
    p[tid]       = a0;
    p[tid + 256] = a1;
    if (tid == 0) {
        g_pm[b * NBPB + blk] = M;
        g_ps[b * NBPB + blk] = S;
    }
}

// ============================================================
// Kernel E: combine 32 partials (8-way float4) -> xa; xa@Wv; @Wp; LayerNorm
// grid: NB, 1024 threads
// ============================================================
__global__ void kE(const float* __restrict__ Wv,
                   const float* __restrict__ Wp,
                   const float* __restrict__ gamma,
                   const float* __restrict__ beta) {
    const int b = blockIdx.x;
    const int tid = threadIdx.x;
    const int warp = tid >> 5, lane = tid & 31;

    __shared__ float spm[NBPB], sps[NBPB], sf[NBPB];
    __shared__ float4 xpart[8][NNE / 4];
    __shared__ float xa[NNE];
    __shared__ float wpart[16][NHS];
    __shared__ float outh[NHS];
    __shared__ float red[32];
    __shared__ float bcast;

    if (tid < NBPB) {
        spm[tid] = g_pm[b * NBPB + tid];
        sps[tid] = g_ps[b * NBPB + tid];
    }
    __syncthreads();

    float mb = -INFINITY;
    #pragma unroll
    for (int c = 0; c < NBPB; ++c) mb = fmaxf(mb, spm[c]);

    if (tid < NBPB) sf[tid] = __expf(spm[tid] - mb);
    __syncthreads();

    float Sb = 0.f;
    #pragma unroll
    for (int c = 0; c < NBPB; ++c) Sb += sps[c] * sf[c];

    {
        const int col4 = tid & 127;
        const int part = tid >> 7;        // 8 parts x 4 partials
        const float4* pp = reinterpret_cast<const float4*>(
            g_pacc + (size_t)(b * NBPB + part * 4) * NNE);
        const float* f = sf + part * 4;
        float4 a = make_float4(0.f, 0.f, 0.f, 0.f);
        #pragma unroll
        for (int c = 0; c < 4; ++c) {
            const float4 v = pp[(size_t)c * 128 + col4];
            const float fc = f[c];
            a.x = fmaf(v.x, fc, a.x);
            a.y = fmaf(v.y, fc, a.y);
            a.z = fmaf(v.z, fc, a.z);
            a.w = fmaf(v.w, fc, a.w);
        }
        xpart[part][col4] = a;
    }
    __syncthreads();
    if (tid < 128) {
        float4 a = xpart[0][tid];
        #pragma unroll
        for (int p = 1; p < 8; ++p) {
            const float4 v = xpart[p][tid];
            a.x += v.x; a.y += v.y; a.z += v.z; a.w += v.w;
        }
        const float inv = 1.f / Sb;
        reinterpret_cast<float4*>(xa)[tid] =
            make_float4(a.x * inv, a.y * inv, a.z * inv, a.w * inv);
    }
    __syncthreads();

    {
        const int h = tid & 63;
        const int part = tid >> 6;
        float po = 0.f;
        #pragma unroll
        for (int n = part * 32; n < part * 32 + 32; ++n)
            po = fmaf(xa[n], Wv[n * NHS + h], po);
        wpart[part][h] = po;
    }
    __syncthreads();
    if (tid < NHS) {
        float o = 0.f;
        #pragma unroll
        for (int p = 0; p < 16; ++p) o += wpart[p][tid];
        outh[tid] = o;
    }
    __syncthreads();

    float y = 0.f;
    if (tid < NNE) {
        #pragma unroll
        for (int h2 = 0; h2 < NHS; ++h2)
            y = fmaf(outh[h2], Wp[h2 * NNE + tid], y);
    }

    float s = (tid < NNE) ? y : 0.f;
    #pragma unroll
    for (int o = 16; o > 0; o >>= 1)
        s += __shfl_xor_sync(0xffffffffu, s, o);
    if (lane == 0) red[warp] = s;
    __syncthreads();
    if (tid < 32) {
        float ss2 = red[tid];
        #pragma unroll
        for (int o = 16; o > 0; o >>= 1)
            ss2 += __shfl_xor_sync(0xffffffffu, ss2, o);
        if (tid == 0) bcast = ss2;
    }
    __syncthreads();
    const float mu = bcast * (1.f / NNE);
    __syncthreads();

    const float d = (tid < NNE) ? (y - mu) : 0.f;
    float vs = d * d;
    #pragma unroll
    for (int o = 16; o > 0; o >>= 1)
        vs += __shfl_xor_sync(0xffffffffu, vs, o);
    if (lane == 0) red[warp] = vs;
    __syncthreads();
    if (tid < 32) {
        float ss2 = red[tid];
        #pragma unroll
        for (int o = 16; o > 0; o >>= 1)
            ss2 += __shfl_xor_sync(0xffffffffu, ss2, o);
        if (tid == 0) bcast = ss2;
    }
    __syncthreads();
    const float var = bcast * (1.f / NNE);
    const float rstd = rsqrtf(var + 1e-5f);

    if (tid < NNE)
        g_y[b * NNE + tid] = d * rstd * gamma[tid] + beta[tid];
}

// ============================================================
// Kernel F: broadcast g_y[b,:] to out[b, t, :]; streaming float4 stores
// ============================================================
#define ROWS_F 64
__global__ void kF(float* __restrict__ out) {
    const int b = blockIdx.y;
    const int tid = threadIdx.x;
    const int col = tid & 127;
    const int half = tid >> 7;

    const float4 val = reinterpret_cast<const float4*>(g_y + b * NNE)[col];

    const int t0 = blockIdx.x * ROWS_F;
    float4* o = reinterpret_cast<float4*>(out + ((size_t)b * NT + t0) * NNE);
    #pragma unroll 8
    for (int r = 0; r < ROWS_F / 2; ++r)
        __stcs(&o[(size_t)(r * 2 + half) * (NNE / 4) + col], val);
}

// ============================================================
extern "C" void kernel_launch(void* const* d_in, const int* in_sizes, int n_in,
                              void* d_out, int out_size) {
    const float* x       = (const float*)d_in[0];
    const float* cat_emb = (const float*)d_in[1];
    const float* Wq      = (const float*)d_in[2];
    const float* Wk      = (const float*)d_in[3];
    const float* Wv      = (const float*)d_in[4];
    const float* Wp      = (const float*)d_in[5];
    const float* gamma   = (const float*)d_in[6];
    const float* beta    = (const float*)d_in[7];
    float* out = (float*)d_out;

    kA<<<NB, 512>>>(cat_emb, Wq, Wk);
    kFuse9<<<dim3(NBPB, NB), 256>>>(x);
    kE<<<NB, 1024>>>(Wv, Wp, gamma, beta);
    kF<<<dim3(NT / ROWS_F, NB), 256>>>(out);
}